// round 11
// baseline (speedup 1.0000x reference)
#include <cuda_runtime.h>
#include <stdint.h>

#define NW      12
#define DIM     4096
#define THREADS 256

typedef unsigned long long u64;

// ---------------------------------------------------------------------------
// GF(2) machinery. CNOT chain = index relabel p -> M p; amplitudes stored in
// q = M p basis where each layer-1 gate is a single-bit-stride gate
// (wire w <-> q bit 11-w). Measurement masks are rows of M; their
// {bit0,bit9..11} parts are {7,12,14,15} in phase-3 register space
// -> Walsh-Hadamard epilogue. M^-1 columns for q bits 1..4 live in p's low
// 6 bits -> chi factor constant per thread in phase 1 (init = 17 LDS).
// Layer-1 RY = cos * [1,-t;t,1]; prod(cos)^2 applied at the end.
// Phase1->2 exchange is intra-warp (syncwarp, not syncthreads).
// Phase-3 loads are LDS.128 q0-pairs; odd-base threads get swapped pairs,
// fixed by negating t in the bit-0 gate and sign-flipping odd WHT outputs.
// ---------------------------------------------------------------------------

struct CircuitMasks {
    int minv_col[12];   // bit-space columns of M^-1
    int pr16[16];       // XOR combos of minv_col[1..4] (low-6-bit masks)
};

static inline int wire2bits(unsigned wiremask) {
    int m = 0;
    for (int v = 0; v < NW; v++)
        if ((wiremask >> v) & 1) m |= 1 << (11 - v);
    return m;
}

static void compute_masks(CircuitMasks* cm) {
    unsigned M[NW];
    for (int w = 0; w < NW; w++) M[w] = 1u << w;
    for (int w = 0; w < NW - 1; w++) M[w + 1] ^= M[w];
    M[0] ^= M[NW - 1];

    unsigned A[NW], Inv[NW];
    for (int i = 0; i < NW; i++) { A[i] = M[i]; Inv[i] = 1u << i; }
    for (int col = 0; col < NW; col++) {
        int piv = -1;
        for (int r = col; r < NW; r++)
            if ((A[r] >> col) & 1) { piv = r; break; }
        unsigned ta = A[col]; A[col] = A[piv]; A[piv] = ta;
        unsigned ti = Inv[col]; Inv[col] = Inv[piv]; Inv[piv] = ti;
        for (int r = 0; r < NW; r++)
            if (r != col && ((A[r] >> col) & 1)) { A[r] ^= A[col]; Inv[r] ^= Inv[col]; }
    }
    unsigned colw[NW];
    for (int w = 0; w < NW; w++) {
        unsigned c = 0;
        for (int v = 0; v < NW; v++)
            if ((Inv[v] >> w) & 1) c |= 1u << v;
        colw[w] = c;
    }

    for (int j = 0; j < NW; j++) cm->minv_col[j] = wire2bits(colw[11 - j]);
    for (int r = 0; r < 16; r++) {
        int p = 0;
        if (r & 1) p ^= cm->minv_col[1];
        if (r & 2) p ^= cm->minv_col[2];
        if (r & 4) p ^= cm->minv_col[3];
        if (r & 8) p ^= cm->minv_col[4];
        cm->pr16[r] = p;
    }
}

// ---------------------------------------------------------------------------
// Device
// ---------------------------------------------------------------------------

// packed f32x2 helpers (Blackwell FFMA2 path)
__device__ __forceinline__ u64 pack2(float a, float b) {
    u64 r; asm("mov.b64 %0, {%1, %2};" : "=l"(r) : "f"(a), "f"(b)); return r;
}
__device__ __forceinline__ u64 ffma2(u64 a, u64 b, u64 c) {
    u64 d; asm("fma.rn.f32x2 %0, %1, %2, %3;" : "=l"(d) : "l"(a), "l"(b), "l"(c)); return d;
}
__device__ __forceinline__ float2 u2f(u64 a) {
    float2 f; asm("mov.b64 {%0, %1}, %2;" : "=f"(f.x), "=f"(f.y) : "l"(a)); return f;
}

// GF(2)-linear state swizzle: conflict-free for all phase patterns.
__device__ __forceinline__ int sw(int q) {
    return q ^ ((q >> 5) & 0xE) ^ ((q >> 4) & 1);
}
// table-entry swizzle: puts index bits 4,5 into bank bits
__device__ __forceinline__ int tsw(int m) { return m ^ ((m >> 3) & 6); }

__global__ __launch_bounds__(THREADS, 5) void qsim_kernel(
    const float* __restrict__ state_batch,
    const float* __restrict__ params,
    const float* __restrict__ head_w,
    const float* __restrict__ head_b,
    float* __restrict__ out,
    CircuitMasks cm) {
    __shared__ __align__(16) u64 s[DIM];
    __shared__ float2 f0[NW], f1[NW];     // per-wire product-state factors
    __shared__ float2 clo[64], chi[64];   // product tables (tsw-swizzled slots)
    __shared__ float  gt[NW];             // layer-1 RY tan per wire
    __shared__ float  cw2[NW];            // layer-1 RY cos^2 per wire
    __shared__ float  shw[NW];            // head_w
    __shared__ float  sCsq;               // prod cos^2
    __shared__ float  red[8];

    const int tid = threadIdx.x;
    const int b = blockIdx.x;

    // --- warp 0: per-wire angles; lane 12 folds prod(cos^2)
    if (tid < 32) {
        if (tid < NW) {
            int w = tid;
            float ang = state_batch[(size_t)b * DIM + w];
            float th = 0.5f * (ang + params[w * 2 + 0]);
            float ph = 0.5f * params[w * 2 + 1];
            float sh, ch_, sp, cp;
            __sincosf(th, &sh, &ch_);
            __sincosf(ph, &sp, &cp);
            f0[w] = make_float2(cp * ch_, -sp * ch_);
            f1[w] = make_float2(cp * sh, sp * sh);
            float t2 = 0.5f * params[2 * NW + w * 2 + 0];
            float s2, c2;
            __sincosf(t2, &s2, &c2);
            gt[w] = s2 / c2;
            cw2[w] = c2 * c2;
            shw[w] = head_w[w];
        }
        __syncwarp();
        if (tid == 12) {
            float P = 1.f;
#pragma unroll
            for (int w = 0; w < NW; w++) P *= cw2[w];
            sCsq = P;
        }
    }

    // --- warps 0-3: product tables (named barrier, warps 4-7 unaffected)
    if (tid < 128) {
        asm volatile("bar.sync 1, 128;" ::: "memory");
        int m = tid & 63;
        bool hi = tid >= 64;
        float2 acc = make_float2(1.f, 0.f);
#pragma unroll
        for (int j = 0; j < 6; j++) {
            int bit = (m >> j) & 1;
            int w = hi ? (5 - j) : (11 - j);
            float2 f = bit ? f1[w] : f0[w];
            acc = make_float2(acc.x * f.x - acc.y * f.y,
                              acc.x * f.y + acc.y * f.x);
        }
        if (hi) chi[tsw(m)] = acc; else clo[tsw(m)] = acc;
    }
    __syncthreads();

    // --- init 16 amplitudes (phase-1 order: regs = q bits 1..4)
    // q: bit0 = tid&1, bits 5..11 = tid bits 1..7
    int pb = 0;
    if (tid & 1) pb ^= cm.minv_col[0];
#pragma unroll
    for (int i = 1; i < 8; i++)
        if ((tid >> i) & 1) pb ^= cm.minv_col[i + 4];

    const float2 hf = chi[tsw((pb >> 6) & 63)];   // constant per thread
    u64 v[16];
#pragma unroll
    for (int r = 0; r < 16; r++) {
        int li = (pb ^ cm.pr16[r]) & 63;
        float2 lo = clo[tsw(li)];
        v[r] = pack2(fmaf(hf.x, lo.x, -hf.y * lo.y),
                     fmaf(hf.x, lo.y,  hf.y * lo.x));
    }

    // tan-form gate on register bit bp with explicit coefficient
#define APPLY_BIT_T(bp, tval) {                                         \
        float t_ = (tval);                                              \
        u64 t2_ = pack2(t_, t_), nt2_ = pack2(-t_, -t_);                \
        _Pragma("unroll")                                               \
        for (int r = 0; r < 16; r++) if (!(r & (1 << bp))) {            \
            int r1 = r | (1 << bp);                                     \
            u64 a_ = v[r], d_ = v[r1];                                  \
            v[r]  = ffma2(nt2_, d_, a_);                                \
            v[r1] = ffma2(t2_,  a_, d_);                                \
        }                                                               \
    }
#define APPLY_BIT(bp, wire) APPLY_BIT_T(bp, gt[wire])

    // --- phase 1: q bits 1..4 -> wires 10,9,8,7
    APPLY_BIT(0, 10); APPLY_BIT(1, 9); APPLY_BIT(2, 8); APPLY_BIT(3, 7);

    const int sb1 = sw((tid & 1) | ((tid >> 1) << 5));
#pragma unroll
    for (int r = 0; r < 16; r++)
        s[sb1 ^ sw(r << 1)] = v[r];
    __syncwarp();   // phase1->2 exchange is intra-warp

    // --- phase 2: regs = q bits 5..8 -> wires 6,5,4,3
    const int sb2 = sw((tid & 31) | ((tid >> 5) << 9));
#pragma unroll
    for (int r = 0; r < 16; r++)
        v[r] = s[sb2 ^ sw(r << 5)];

    APPLY_BIT(0, 6); APPLY_BIT(1, 5); APPLY_BIT(2, 4); APPLY_BIT(3, 3);

#pragma unroll
    for (int r = 0; r < 16; r++)
        s[sb2 ^ sw(r << 5)] = v[r];
    __syncthreads();  // phase2->3 exchange is cross-warp

    // --- phase 3: regs = q bits {0,9,10,11} -> wires 11,2,1,0
    // LDS.128 on q0-pairs; odd-base threads (s3=1) hold pairs swapped.
    const int sb3 = sw(tid << 1);
    const int base3 = sb3 & ~1;
    const int s3 = (tid >> 3) & 1;        // = sb3 & 1
#pragma unroll
    for (int k = 0; k < 8; k++) {
        ulonglong2 t = *reinterpret_cast<ulonglong2*>(&s[base3 ^ (k << 9)]);
        v[2 * k]     = t.x;
        v[2 * k + 1] = t.y;
    }

    APPLY_BIT_T(0, s3 ? -gt[11] : gt[11]);   // swapped pair <=> RY(-t)
    APPLY_BIT(1, 2); APPLY_BIT(2, 1); APPLY_BIT(3, 0);

    // --- Walsh-Hadamard measurement over the 16 per-thread probabilities.
    // reg bit 0 <-> q0 (s3-swapped), bits 1..3 <-> q9..q11. Outputs 7,12,14,15.
    float prob[16];
#pragma unroll
    for (int r = 0; r < 16; r++) {
        float2 a = u2f(v[r]);
        prob[r] = fmaf(a.x, a.x, a.y * a.y);
    }
#pragma unroll
    for (int k = 0; k < 4; k++) {
        int st = 1 << k;
#pragma unroll
        for (int r = 0; r < 16; r++) if (!(r & st)) {
            float a0 = prob[r], b0 = prob[r | st];
            prob[r] = a0 + b0;
            prob[r | st] = a0 - b0;
        }
    }
    // tid bits t_i <-> q bits i+1. Cumulative parities from the top bit.
    int b7 = (tid >> 7) & 1, b6 = (tid >> 6) & 1, b5 = (tid >> 5) & 1,
        b4 = (tid >> 4) & 1, b3 = (tid >> 3) & 1, b2 = (tid >> 2) & 1,
        b1 = (tid >> 1) & 1, b0 = tid & 1;
    int p7 = b7, p6 = p7 ^ b6, p5 = p6 ^ b5, p4 = p5 ^ b4,
        p3 = p4 ^ b3, p2 = p3 ^ b2, p1 = p2 ^ b1, p0 = p1 ^ b0;
    const int p0e = p0 ^ s3;              // bit0-swap flips odd WHT outputs
    float W14 = shw[2];
    W14 += p7 ? -shw[3]  : shw[3];
    W14 += p6 ? -shw[4]  : shw[4];
    W14 += p5 ? -shw[5]  : shw[5];
    W14 += p4 ? -shw[6]  : shw[6];
    W14 += p3 ? -shw[7]  : shw[7];
    W14 += p2 ? -shw[8]  : shw[8];
    W14 += p1 ? -shw[9]  : shw[9];
    W14 += p0 ? -shw[10] : shw[10];
    float A7  = p0e ? -shw[0]  : shw[0];
    float A15 = p0e ? -shw[11] : shw[11];

    float acc = A7 * prob[7];
    acc = fmaf(shw[1], prob[12], acc);
    acc = fmaf(W14,    prob[14], acc);
    acc = fmaf(A15,    prob[15], acc);

#pragma unroll
    for (int o = 16; o > 0; o >>= 1)
        acc += __shfl_xor_sync(0xffffffffu, acc, o);
    if ((tid & 31) == 0) red[tid >> 5] = acc;
    __syncthreads();
    if (tid == 0) {
        float t = 0.f;
#pragma unroll
        for (int i = 0; i < 8; i++) t += red[i];
        out[b] = fmaf(t, sCsq, head_b[0]);
    }
#undef APPLY_BIT
#undef APPLY_BIT_T
}

// ---------------------------------------------------------------------------

extern "C" void kernel_launch(void* const* d_in, const int* in_sizes, int n_in,
                              void* d_out, int out_size) {
    const float* state_batch = (const float*)d_in[0];
    const float* params      = (const float*)d_in[1];
    const float* head_w      = (const float*)d_in[2];
    const float* head_b      = (const float*)d_in[3];
    float* out = (float*)d_out;

    CircuitMasks cm;
    compute_masks(&cm);

    qsim_kernel<<<out_size, THREADS>>>(state_batch, params, head_w, head_b, out, cm);
}

// round 13
// speedup vs baseline: 1.0756x; 1.0756x over previous
#include <cuda_runtime.h>
#include <stdint.h>

#define NW      12
#define DIM     4096
#define THREADS 256

typedef unsigned long long u64;

// ---------------------------------------------------------------------------
// All GF(2) circuit constants are FIXED by the problem and hard-coded.
// CNOT chain = relabel p -> M p (M rows: w>=1 prefix masks, w=0 = e1^..^e11).
// Amplitudes stored in q = M p basis: layer-1 gate on wire w pairs along
// q bit (11-w). M^-1: x0=y0^y11, x1=y0^y1^y11, xw=y_{w-1}^yw  =>
// bit-space columns: minv_col[0]=0xC01, minv_col[j]=0x3<<(j-1) (j=1..10),
// minv_col[11]=0xC00.  (Verified against host Gauss-Jordan of R10/R11.)
// Measurement masks (rows of M) restricted to q bits {0,9,10,11} give WHT
// outputs {7,12,14,15}. Layer-1 RY = cos * [1,-t;t,1]; prod cos^2 folded at
// the end. Phase1->2 exchange intra-warp. Phase-3 loads are LDS.128 pairs
// (odd-base swap fixed by negating t and sign-flipping odd WHT outputs).
// Within each phase, bit-0/1/2 gates act independently on v[0..7]/v[8..15],
// so loads of the upper half are overlapped with gates on the lower half.
// ---------------------------------------------------------------------------

// packed f32x2 helpers (Blackwell FFMA2 path)
__device__ __forceinline__ u64 pack2(float a, float b) {
    u64 r; asm("mov.b64 %0, {%1, %2};" : "=l"(r) : "f"(a), "f"(b)); return r;
}
__device__ __forceinline__ u64 ffma2(u64 a, u64 b, u64 c) {
    u64 d; asm("fma.rn.f32x2 %0, %1, %2, %3;" : "=l"(d) : "l"(a), "l"(b), "l"(c)); return d;
}
__device__ __forceinline__ float2 u2f(u64 a) {
    float2 f; asm("mov.b64 {%0, %1}, %2;" : "=f"(f.x), "=f"(f.y) : "l"(a)); return f;
}

// GF(2)-linear state swizzle: conflict-free for all phase patterns.
__device__ __forceinline__ constexpr int sw(int q) {
    return q ^ ((q >> 5) & 0xE) ^ ((q >> 4) & 1);
}
// table-entry swizzle: puts index bits 4,5 into bank bits
__device__ __forceinline__ constexpr int tsw(int m) { return m ^ ((m >> 3) & 6); }
// XOR combos of minv cols 1..4 (0x3,0x6,0xC,0x18) — compile-time per r
__device__ __forceinline__ constexpr int pr16c(int r) {
    return ((r & 1) ? 0x3 : 0) ^ ((r & 2) ? 0x6 : 0) ^
           ((r & 4) ? 0xC : 0) ^ ((r & 8) ? 0x18 : 0);
}

__global__ __launch_bounds__(THREADS, 5) void qsim_kernel(
    const float* __restrict__ state_batch,
    const float* __restrict__ params,
    const float* __restrict__ head_w,
    const float* __restrict__ head_b,
    float* __restrict__ out) {
    __shared__ __align__(16) u64 s[DIM];
    __shared__ float2 f0[NW], f1[NW];     // per-wire product-state factors
    __shared__ float2 clo[64], chi[64];   // product tables (tsw-swizzled slots)
    __shared__ float  gt[NW];             // layer-1 RY tan per wire
    __shared__ float  cw2[NW];            // layer-1 RY cos^2 per wire
    __shared__ float  shw[NW];            // head_w
    __shared__ float  sCsq;               // prod cos^2
    __shared__ float  red[8];

    const int tid = threadIdx.x;
    const int b = blockIdx.x;

    // --- warp 0: per-wire angles; lane 12 folds prod(cos^2)
    if (tid < 32) {
        if (tid < NW) {
            int w = tid;
            float ang = state_batch[(size_t)b * DIM + w];
            float th = 0.5f * (ang + params[w * 2 + 0]);
            float ph = 0.5f * params[w * 2 + 1];
            float sh, ch_, sp, cp;
            __sincosf(th, &sh, &ch_);
            __sincosf(ph, &sp, &cp);
            f0[w] = make_float2(cp * ch_, -sp * ch_);
            f1[w] = make_float2(cp * sh, sp * sh);
            float t2 = 0.5f * params[2 * NW + w * 2 + 0];
            float s2, c2;
            __sincosf(t2, &s2, &c2);
            gt[w] = s2 / c2;
            cw2[w] = c2 * c2;
            shw[w] = head_w[w];
        }
        __syncwarp();
        if (tid == 12) {
            float P = 1.f;
#pragma unroll
            for (int w = 0; w < NW; w++) P *= cw2[w];
            sCsq = P;
        }
    }

    // --- warps 0-3: product tables (named barrier; warps 4-7 unaffected)
    if (tid < 128) {
        asm volatile("bar.sync 1, 128;" ::: "memory");
        int m = tid & 63;
        bool hi = tid >= 64;
        float2 acc = make_float2(1.f, 0.f);
#pragma unroll
        for (int j = 0; j < 6; j++) {
            int bit = (m >> j) & 1;
            int w = hi ? (5 - j) : (11 - j);
            float2 f = bit ? f1[w] : f0[w];
            acc = make_float2(acc.x * f.x - acc.y * f.y,
                              acc.x * f.y + acc.y * f.x);
        }
        if (hi) chi[tsw(m)] = acc; else clo[tsw(m)] = acc;
    }
    __syncthreads();

    // --- init: q bit0 = tid&1, bits 5..11 = tid bits 1..7 (hard-coded cols)
    int pb = 0;
    if (tid & 1)   pb ^= 0xC01;  // minv_col[0]
    if (tid & 2)   pb ^= 0x030;  // minv_col[5]
    if (tid & 4)   pb ^= 0x060;  // minv_col[6]
    if (tid & 8)   pb ^= 0x0C0;  // minv_col[7]
    if (tid & 16)  pb ^= 0x180;  // minv_col[8]
    if (tid & 32)  pb ^= 0x300;  // minv_col[9]
    if (tid & 64)  pb ^= 0x600;  // minv_col[10]
    if (tid & 128) pb ^= 0xC00;  // minv_col[11]

    const float2 hf = chi[tsw((pb >> 6) & 63)];   // constant per thread
    u64 v[16];

#define INIT_R(RLO, RHI)                                                \
    _Pragma("unroll")                                                   \
    for (int r = RLO; r < RHI; r++) {                                   \
        int li = (pb ^ pr16c(r)) & 63;                                  \
        float2 lo = clo[tsw(li)];                                       \
        v[r] = pack2(fmaf(hf.x, lo.x, -hf.y * lo.y),                    \
                     fmaf(hf.x, lo.y,  hf.y * lo.x));                   \
    }

    // tan-form gate on register bit bp over [RLO,RHI)
#define APPLY_R(bp, tval, RLO, RHI) {                                   \
        float t_ = (tval);                                              \
        u64 t2_ = pack2(t_, t_), nt2_ = pack2(-t_, -t_);                \
        _Pragma("unroll")                                               \
        for (int r = RLO; r < RHI; r++) if (!(r & (1 << bp))) {         \
            int r1 = r | (1 << bp);                                     \
            u64 a_ = v[r], d_ = v[r1];                                  \
            v[r]  = ffma2(nt2_, d_, a_);                                \
            v[r1] = ffma2(t2_,  a_, d_);                                \
        }                                                               \
    }

    // --- phase 1: regs = q bits 1..4 -> wires 10,9,8,7 (pipelined halves)
    INIT_R(0, 8)
    APPLY_R(0, gt[10], 0, 8); APPLY_R(1, gt[9], 0, 8); APPLY_R(2, gt[8], 0, 8);
    INIT_R(8, 16)
    APPLY_R(0, gt[10], 8, 16); APPLY_R(1, gt[9], 8, 16); APPLY_R(2, gt[8], 8, 16);
    APPLY_R(3, gt[7], 0, 16);

    const int sb1 = sw((tid & 1) | ((tid >> 1) << 5));
#pragma unroll
    for (int r = 0; r < 16; r++)
        s[sb1 ^ sw(r << 1)] = v[r];
    __syncwarp();   // phase1->2 exchange is intra-warp

    // --- phase 2: regs = q bits 5..8 -> wires 6,5,4,3 (pipelined halves)
    const int sb2 = sw((tid & 31) | ((tid >> 5) << 9));
#pragma unroll
    for (int r = 0; r < 8; r++)
        v[r] = s[sb2 ^ sw(r << 5)];
    APPLY_R(0, gt[6], 0, 8); APPLY_R(1, gt[5], 0, 8); APPLY_R(2, gt[4], 0, 8);
#pragma unroll
    for (int r = 8; r < 16; r++)
        v[r] = s[sb2 ^ sw(r << 5)];
    APPLY_R(0, gt[6], 8, 16); APPLY_R(1, gt[5], 8, 16); APPLY_R(2, gt[4], 8, 16);
    APPLY_R(3, gt[3], 0, 16);

#pragma unroll
    for (int r = 0; r < 16; r++)
        s[sb2 ^ sw(r << 5)] = v[r];
    __syncthreads();  // phase2->3 exchange is cross-warp

    // --- phase 3: regs = q bits {0,9,10,11} -> wires 11,2,1,0
    // LDS.128 q0-pairs; odd-base threads (s3=1) hold pairs swapped.
    const int sb3 = sw(tid << 1);
    const int base3 = sb3 & ~1;
    const int s3 = (tid >> 3) & 1;        // = sb3 & 1
    const float t11 = s3 ? -gt[11] : gt[11];
#pragma unroll
    for (int k = 0; k < 4; k++) {
        ulonglong2 t = *reinterpret_cast<ulonglong2*>(&s[base3 ^ (k << 9)]);
        v[2 * k] = t.x; v[2 * k + 1] = t.y;
    }
    APPLY_R(0, t11, 0, 8); APPLY_R(1, gt[2], 0, 8); APPLY_R(2, gt[1], 0, 8);
#pragma unroll
    for (int k = 4; k < 8; k++) {
        ulonglong2 t = *reinterpret_cast<ulonglong2*>(&s[base3 ^ (k << 9)]);
        v[2 * k] = t.x; v[2 * k + 1] = t.y;
    }
    APPLY_R(0, t11, 8, 16); APPLY_R(1, gt[2], 8, 16); APPLY_R(2, gt[1], 8, 16);
    APPLY_R(3, gt[0], 0, 16);

    // --- Walsh-Hadamard measurement over the 16 per-thread probabilities.
    // reg bit 0 <-> q0 (s3-swapped), bits 1..3 <-> q9..q11. Outputs 7,12,14,15.
    float prob[16];
#pragma unroll
    for (int r = 0; r < 16; r++) {
        float2 a = u2f(v[r]);
        prob[r] = fmaf(a.x, a.x, a.y * a.y);
    }
#pragma unroll
    for (int k = 0; k < 4; k++) {
        int st = 1 << k;
#pragma unroll
        for (int r = 0; r < 16; r++) if (!(r & st)) {
            float a0 = prob[r], b0 = prob[r | st];
            prob[r] = a0 + b0;
            prob[r | st] = a0 - b0;
        }
    }
    // tid bits t_i <-> q bits i+1. Cumulative parities from the top bit.
    int b7 = (tid >> 7) & 1, b6 = (tid >> 6) & 1, b5 = (tid >> 5) & 1,
        b4 = (tid >> 4) & 1, b3 = (tid >> 3) & 1, b2 = (tid >> 2) & 1,
        b1 = (tid >> 1) & 1, b0 = tid & 1;
    int p7 = b7, p6 = p7 ^ b6, p5 = p6 ^ b5, p4 = p5 ^ b4,
        p3 = p4 ^ b3, p2 = p3 ^ b2, p1 = p2 ^ b1, p0 = p1 ^ b0;
    const int p0e = p0 ^ s3;              // bit0-swap flips odd WHT outputs
    float W14 = shw[2];
    W14 += p7 ? -shw[3]  : shw[3];
    W14 += p6 ? -shw[4]  : shw[4];
    W14 += p5 ? -shw[5]  : shw[5];
    W14 += p4 ? -shw[6]  : shw[6];
    W14 += p3 ? -shw[7]  : shw[7];
    W14 += p2 ? -shw[8]  : shw[8];
    W14 += p1 ? -shw[9]  : shw[9];
    W14 += p0 ? -shw[10] : shw[10];
    float A7  = p0e ? -shw[0]  : shw[0];
    float A15 = p0e ? -shw[11] : shw[11];

    float acc = A7 * prob[7];
    acc = fmaf(shw[1], prob[12], acc);
    acc = fmaf(W14,    prob[14], acc);
    acc = fmaf(A15,    prob[15], acc);

#pragma unroll
    for (int o = 16; o > 0; o >>= 1)
        acc += __shfl_xor_sync(0xffffffffu, acc, o);
    if ((tid & 31) == 0) red[tid >> 5] = acc;
    __syncthreads();
    if (tid == 0) {
        float t = 0.f;
#pragma unroll
        for (int i = 0; i < 8; i++) t += red[i];
        out[b] = fmaf(t, sCsq, head_b[0]);
    }
#undef APPLY_R
#undef INIT_R
}

// ---------------------------------------------------------------------------

extern "C" void kernel_launch(void* const* d_in, const int* in_sizes, int n_in,
                              void* d_out, int out_size) {
    const float* state_batch = (const float*)d_in[0];
    const float* params      = (const float*)d_in[1];
    const float* head_w      = (const float*)d_in[2];
    const float* head_b      = (const float*)d_in[3];
    float* out = (float*)d_out;

    qsim_kernel<<<out_size, THREADS>>>(state_batch, params, head_w, head_b, out);
}

// round 14
// speedup vs baseline: 1.5091x; 1.4030x over previous
#include <cuda_runtime.h>

#define NW  12
#define DIM 4096
#define TPB 64

// ---------------------------------------------------------------------------
// Transfer-matrix evaluation of the circuit, O(NW) per batch element.
//
// Heisenberg picture: out_w = <psi| C† R† C† Z_w C R C |psi>.
//   C|x> = |Mx>  (M rows: row_w = e0^..^ew for w>=1, row_0 = e1^..^e11 —
//   verified against the passing state-vector kernel).
//   C† Z_w C = Z_{S_w},  S_w = supp(row_w): {0..w} for w>=1, {1..11} for w=0.
//   R† Z_S R = ⊗_{v∈S} D_v,  D_v = cos(t1_v) Z − sin(t1_v) X  (t1 FULL angle;
//   verified: RY(θ)† Z RY(θ) = cosθ Z − sinθ X). Layer-1 RZ commutes out.
//   |chi> = C|psi_prod>, chi(y) = Π_w f_w(x_w), x = M^{-1}y. Summing over x:
//   y_v = P_v := x_0^..^x_v (v>=1), y_0 = P_11 ^ x_0.
//   <chi|⊗O_v|chi> contracts as a chain over pair-state (P_v, P'_v):
//     T_v[(Pn,P'n)<-(Pp,P'p)] = f_v(Pp^Pn) conj(f_v)(P'p^P'n) (O_v)_{P'n,Pn}
//   Site 0 is the boundary: 4 columns (g,g') = (x_0, x'_0); cap applies
//   f_0(g) conj(f_0)(g') and D_0 (or δ for w=0) at y_0 = P_11^g.
//   Identity sites force P'=P: first one is a 2x4 "bridge", the rest are
//   real 2x2 [[n0,n1],[n1,n0]] with n_b = |f(b)|^2 (n0+n1=1).
//   Nested S_w ⇒ one forward sweep of active T_v yields all outputs.
// ---------------------------------------------------------------------------

__global__ __launch_bounds__(TPB) void qtm_kernel(
    const float* __restrict__ state_batch,
    const float* __restrict__ params,
    const float* __restrict__ head_w,
    const float* __restrict__ head_b,
    float* __restrict__ out, int nbatch) {
    int b = blockIdx.x * blockDim.x + threadIdx.x;
    if (b >= nbatch) return;

    // --- per-wire factors: f_w(0), f_w(1) of RZ(phi) RY(ang+t0)|0>, D angles
    float f0r[NW], f0i[NW], f1r[NW], f1i[NW], cg[NW], sg[NW], hw[NW];
#pragma unroll
    for (int w = 0; w < NW; w++) {
        float ang = state_batch[(size_t)b * DIM + w];
        float th = 0.5f * (ang + params[2 * w]);
        float ph = 0.5f * params[2 * w + 1];
        float sh, ch, sp, cp;
        __sincosf(th, &sh, &ch);
        __sincosf(ph, &sp, &cp);
        f0r[w] = cp * ch; f0i[w] = -sp * ch;
        f1r[w] = cp * sh; f1i[w] =  sp * sh;
        float t1 = params[2 * NW + 2 * w];       // FULL angle for D
        __sincosf(t1, &sg[w], &cg[w]);
        hw[w] = head_w[w];
    }

    // --- identity-tail products N(w) = Tid_11 ... Tid_{w+2} = [[A,B],[B,A]]
    float NA[11], NB[11];
    NA[10] = 1.f; NB[10] = 0.f;
#pragma unroll
    for (int w = 9; w >= 1; w--) {
        int u = w + 2;
        float n0 = f0r[u] * f0r[u] + f0i[u] * f0i[u];
        float n1 = f1r[u] * f1r[u] + f1i[u] * f1i[u];
        NA[w] = NA[w + 1] * n0 + NB[w + 1] * n1;
        NB[w] = NA[w + 1] * n1 + NB[w + 1] * n0;
    }

    // --- boundary weights W[col] = f_0(g) conj(f_0(g')), col = g + 2g'
    float Wr[4], Wi[4];
#pragma unroll
    for (int col = 0; col < 4; col++) {
        int g = col & 1, gp = col >> 1;
        float ar = g ? f1r[0] : f0r[0], ai = g ? f1i[0] : f0i[0];
        float br = gp ? f1r[0] : f0r[0], bi = gp ? f1i[0] : f0i[0];
        Wr[col] = ar * br + ai * bi;
        Wi[col] = ai * br - ar * bi;
    }

    // --- forward 4x4 complex M (pair state idx = P + 2P'), init identity
    float Mr[4][4], Mi[4][4];
#pragma unroll
    for (int i = 0; i < 4; i++)
#pragma unroll
        for (int j = 0; j < 4; j++) { Mr[i][j] = (i == j) ? 1.f : 0.f; Mi[i][j] = 0.f; }

    float o = head_b[0];
    const float c0 = cg[0], s0 = sg[0];

#pragma unroll
    for (int v = 1; v <= 11; v++) {
        const float fr0 = f0r[v], fi0 = f0i[v], fr1 = f1r[v], fi1 = f1i[v];
        const float cv = cg[v], sv = sg[v];
#pragma unroll
        for (int col = 0; col < 4; col++) {
            float m0r = Mr[0][col], m0i = Mi[0][col];   // (P,P')=(0,0)
            float m1r = Mr[1][col], m1i = Mi[1][col];   // (1,0)
            float m2r = Mr[2][col], m2i = Mi[2][col];   // (0,1)
            float m3r = Mr[3][col], m3i = Mi[3][col];   // (1,1)
            // A: a[Pn][P'p] = f(0)m[Pn][P'p] + f(1)m[Pn^1][P'p]
            float a00r = fr0*m0r - fi0*m0i + fr1*m1r - fi1*m1i;
            float a00i = fr0*m0i + fi0*m0r + fr1*m1i + fi1*m1r;
            float a10r = fr1*m0r - fi1*m0i + fr0*m1r - fi0*m1i;
            float a10i = fr1*m0i + fi1*m0r + fr0*m1i + fi0*m1r;
            float a01r = fr0*m2r - fi0*m2i + fr1*m3r - fi1*m3i;
            float a01i = fr0*m2i + fi0*m2r + fr1*m3i + fi1*m3r;
            float a11r = fr1*m2r - fi1*m2i + fr0*m3r - fi0*m3i;
            float a11i = fr1*m2i + fi1*m2r + fr0*m3i + fi0*m3r;
            // B: b[Pn][P'n] = cf(0)a[Pn][P'n] + cf(1)a[Pn][P'n^1]; cf*z=(fr zr+fi zi, fr zi−fi zr)
            float b00r = fr0*a00r + fi0*a00i + fr1*a01r + fi1*a01i;
            float b00i = fr0*a00i - fi0*a00r + fr1*a01i - fi1*a01r;
            float b10r = fr0*a10r + fi0*a10i + fr1*a11r + fi1*a11i;
            float b10i = fr0*a10i - fi0*a10r + fr1*a11i - fi1*a11r;
            float b01r = fr1*a00r + fi1*a00i + fr0*a01r + fi0*a01i;
            float b01i = fr1*a00i - fi1*a00r + fr0*a01i - fi0*a01r;
            float b11r = fr1*a10r + fi1*a10i + fr0*a11r + fi0*a11i;
            float b11i = fr1*a10i - fi1*a10r + fr0*a11i - fi0*a11r;
            // C: × D[P'n][Pn]: (0,0):c  (1,0):−s  (0,1):−s  (1,1):−c
            Mr[0][col] =  cv*b00r; Mi[0][col] =  cv*b00i;
            Mr[1][col] = -sv*b10r; Mi[1][col] = -sv*b10i;
            Mr[2][col] = -sv*b01r; Mi[2][col] = -sv*b01i;
            Mr[3][col] = -cv*b11r; Mi[3][col] = -cv*b11i;
        }
        if (v <= 10) {
            // output wire v: bridge at u=v+1 (identity, P'=P), tail N(v), cap at site 0
            const int u = v + 1;
            const float gr0 = f0r[u], gi0 = f0i[u], gr1 = f1r[u], gi1 = f1i[u];
            float accr = 0.f;
#pragma unroll
            for (int col = 0; col < 4; col++) {
                float m0r = Mr[0][col], m0i = Mi[0][col];
                float m1r = Mr[1][col], m1i = Mi[1][col];
                float m2r = Mr[2][col], m2i = Mi[2][col];
                float m3r = Mr[3][col], m3i = Mi[3][col];
                // e[h][P'p] = f_u(0)m[h][P'p] + f_u(1)m[h^1][P'p]
                float e00r = gr0*m0r - gi0*m0i + gr1*m1r - gi1*m1i;
                float e00i = gr0*m0i + gi0*m0r + gr1*m1i + gi1*m1r;
                float e01r = gr0*m2r - gi0*m2i + gr1*m3r - gi1*m3i;
                float e01i = gr0*m2i + gi0*m2r + gr1*m3i + gi1*m3r;
                float e10r = gr1*m0r - gi1*m0i + gr0*m1r - gi0*m1i;
                float e10i = gr1*m0i + gi1*m0r + gr0*m1i + gi0*m1r;
                float e11r = gr1*m2r - gi1*m2i + gr0*m3r - gi0*m3i;
                float e11i = gr1*m2i + gi1*m2r + gr0*m3i + gi0*m3r;
                // t[h]: t0 = cf0 e00 + cf1 e01 ; t1 = cf1 e10 + cf0 e11
                float t0r = gr0*e00r + gi0*e00i + gr1*e01r + gi1*e01i;
                float t0i = gr0*e00i - gi0*e00r + gr1*e01i - gi1*e01r;
                float t1r = gr1*e10r + gi1*e10i + gr0*e11r + gi0*e11i;
                float t1i = gr1*e10i - gi1*e10r + gr0*e11i - gi0*e11r;
                // z = N(v) t
                float z0r = NA[v]*t0r + NB[v]*t1r, z0i = NA[v]*t0i + NB[v]*t1i;
                float z1r = NB[v]*t0r + NA[v]*t1r, z1i = NB[v]*t0i + NA[v]*t1i;
                // cap: y0 = h^g, y0' = h^g'
                int g = col & 1, gp = col >> 1;
                float Sr, Si;
                if (g == gp) {
                    float d0 = g ? -c0 : c0;          // h=0 value; h=1 is −d0
                    Sr = d0 * (z0r - z1r); Si = d0 * (z0i - z1i);
                } else {
                    Sr = -s0 * (z0r + z1r); Si = -s0 * (z0i + z1i);
                }
                accr += Wr[col] * Sr - Wi[col] * Si;   // Re(W·S)
            }
            o += hw[v] * accr;
        }
    }

    // --- outputs for wires 11 (site 0 active) and 0 (site 0 identity) from M(11)
    {
        float acc11 = 0.f, acc0 = 0.f;
#pragma unroll
        for (int col = 0; col < 4; col++) {
            int g = col & 1, gp = col >> 1;
#pragma unroll
            for (int idx = 0; idx < 4; idx++) {
                int h = idx & 1, hp = idx >> 1;
                int y = h ^ g, yp = hp ^ gp;
                float mr = Mr[idx][col], mi = Mi[idx][col];
                float wmr = Wr[col] * mr - Wi[col] * mi;   // Re(W·m)
                float Dv = (y == yp) ? (y ? -c0 : c0) : (-s0);
                acc11 += Dv * wmr;
                if (y == yp) acc0 += wmr;
            }
        }
        o += hw[11] * acc11 + hw[0] * acc0;
    }

    out[b] = o;
}

// ---------------------------------------------------------------------------

extern "C" void kernel_launch(void* const* d_in, const int* in_sizes, int n_in,
                              void* d_out, int out_size) {
    const float* state_batch = (const float*)d_in[0];
    const float* params      = (const float*)d_in[1];
    const float* head_w      = (const float*)d_in[2];
    const float* head_b      = (const float*)d_in[3];
    float* out = (float*)d_out;

    int blocks = (out_size + TPB - 1) / TPB;
    qtm_kernel<<<blocks, TPB>>>(state_batch, params, head_w, head_b, out, out_size);
}

// round 15
// speedup vs baseline: 2.4175x; 1.6019x over previous
#include <cuda_runtime.h>

#define NW  12
#define DIM 4096
#define TPB 32

// ---------------------------------------------------------------------------
// Transfer-matrix evaluation, O(NW) per batch element, 4 threads per element
// (one per boundary column (g,g') of the 4x4 pair-state transfer chain; the
// columns evolve independently, outputs reduce over columns via shuffles).
//
// Heisenberg picture: out_w = <psi| C† R† C† Z_w C R C |psi>.
//   C|x> = |Mx> (M rows: row_w = e0^..^ew for w>=1, row_0 = e1^..^e11).
//   C† Z_w C = Z_{S_w}; R† Z_S R = ⊗_{v∈S} D_v, D_v = cos(t1_v)Z − sin(t1_v)X
//   (t1 FULL angle). Layer-1 RZ commutes out.
//   chi(y) = Π f_w(x_w), y_v = P_v = x_0^..^x_v (v>=1), y_0 = P_11^x_0.
//   Chain over (P_v,P'_v); site 0 = boundary column (g,g') = (x_0,x'_0) with
//   weight W = f_0(g) conj(f_0(g')) and cap D_0 (δ for wire 0) at y_0 = h^g.
//   Identity sites: first is a 2x4 bridge, rest collapse to real 2x2
//   [[NA,1-NA],[1-NA,NA]]. Nested S_w ⇒ one forward sweep gives all outputs.
// All formulas identical to the R14-passing kernel; only the col loop is
// distributed across lanes.
// ---------------------------------------------------------------------------

__global__ __launch_bounds__(TPB) void qtm_kernel(
    const float* __restrict__ state_batch,
    const float* __restrict__ params,
    const float* __restrict__ head_w,
    const float* __restrict__ head_b,
    float* __restrict__ out, int nbatch) {
    const int gtid = blockIdx.x * TPB + threadIdx.x;
    const int b = gtid >> 2;          // batch element
    const int col = gtid & 3;         // boundary column (g,g')
    if (b >= nbatch) return;          // whole quad exits together

    const int g = col & 1, gp = col >> 1;

    // --- per-wire factors (redundant across the 4 lanes of an element)
    float f0r[NW], f0i[NW], f1r[NW], f1i[NW], cg[NW], sg[NW], hw[NW];
#pragma unroll
    for (int w = 0; w < NW; w++) {
        float ang = state_batch[(size_t)b * DIM + w];
        float th = 0.5f * (ang + params[2 * w]);
        float ph = 0.5f * params[2 * w + 1];
        float sh, ch, sp, cp;
        __sincosf(th, &sh, &ch);
        __sincosf(ph, &sp, &cp);
        f0r[w] = cp * ch; f0i[w] = -sp * ch;
        f1r[w] = cp * sh; f1i[w] =  sp * sh;
        float t1 = params[2 * NW + 2 * w];       // FULL angle for D
        __sincosf(t1, &sg[w], &cg[w]);
        hw[w] = head_w[w];
    }

    // --- identity-tail products N(w): [[NA,1-NA],[1-NA,NA]]
    float NA[11];
    NA[10] = 1.f;
#pragma unroll
    for (int w = 9; w >= 1; w--) {
        int u = w + 2;
        float n0 = f0r[u] * f0r[u] + f0i[u] * f0i[u];   // n1 = 1 - n0
        NA[w] = NA[w + 1] * n0 + (1.f - NA[w + 1]) * (1.f - n0);
    }

    // --- this lane's boundary weight W = f_0(g) conj(f_0(g'))
    float ar = g ? f1r[0] : f0r[0], ai = g ? f1i[0] : f0i[0];
    float br = gp ? f1r[0] : f0r[0], bi = gp ? f1i[0] : f0i[0];
    const float Wr = ar * br + ai * bi;
    const float Wi = ai * br - ar * bi;

    // --- column state: complex 4-vector, pair idx = P + 2P'; init e_col
    float m0r = (col == 0), m0i = 0.f;
    float m1r = (col == 1), m1i = 0.f;
    float m2r = (col == 2), m2i = 0.f;
    float m3r = (col == 3), m3i = 0.f;

    float o = 0.f;
    const float c0 = cg[0], s0 = sg[0];

#pragma unroll
    for (int v = 1; v <= 11; v++) {
        const float fr0 = f0r[v], fi0 = f0i[v], fr1 = f1r[v], fi1 = f1i[v];
        const float cv = cg[v], sv = sg[v];
        // A: a[Pn][P'p] = f(0)m[Pn][P'p] + f(1)m[Pn^1][P'p]
        float a00r = fr0*m0r - fi0*m0i + fr1*m1r - fi1*m1i;
        float a00i = fr0*m0i + fi0*m0r + fr1*m1i + fi1*m1r;
        float a10r = fr1*m0r - fi1*m0i + fr0*m1r - fi0*m1i;
        float a10i = fr1*m0i + fi1*m0r + fr0*m1i + fi0*m1r;
        float a01r = fr0*m2r - fi0*m2i + fr1*m3r - fi1*m3i;
        float a01i = fr0*m2i + fi0*m2r + fr1*m3i + fi1*m3r;
        float a11r = fr1*m2r - fi1*m2i + fr0*m3r - fi0*m3i;
        float a11i = fr1*m2i + fi1*m2r + fr0*m3i + fi0*m3r;
        // B: b[Pn][P'n] = cf(0)a[Pn][P'n] + cf(1)a[Pn][P'n^1]
        float b00r = fr0*a00r + fi0*a00i + fr1*a01r + fi1*a01i;
        float b00i = fr0*a00i - fi0*a00r + fr1*a01i - fi1*a01r;
        float b10r = fr0*a10r + fi0*a10i + fr1*a11r + fi1*a11i;
        float b10i = fr0*a10i - fi0*a10r + fr1*a11i - fi1*a11r;
        float b01r = fr1*a00r + fi1*a00i + fr0*a01r + fi0*a01i;
        float b01i = fr1*a00i - fi1*a00r + fr0*a01i - fi0*a01r;
        float b11r = fr1*a10r + fi1*a10i + fr0*a11r + fi0*a11i;
        float b11i = fr1*a10i - fi1*a10r + fr0*a11i - fi0*a11r;
        // C: × D[P'n][Pn]
        m0r =  cv*b00r; m0i =  cv*b00i;
        m1r = -sv*b10r; m1i = -sv*b10i;
        m2r = -sv*b01r; m2i = -sv*b01i;
        m3r = -cv*b11r; m3i = -cv*b11i;

        if (v <= 10) {
            // output wire v: bridge at u=v+1, tail N(v), cap at site 0
            const int u = v + 1;
            const float gr0 = f0r[u], gi0 = f0i[u], gr1 = f1r[u], gi1 = f1i[u];
            float e00r = gr0*m0r - gi0*m0i + gr1*m1r - gi1*m1i;
            float e00i = gr0*m0i + gi0*m0r + gr1*m1i + gi1*m1r;
            float e01r = gr0*m2r - gi0*m2i + gr1*m3r - gi1*m3i;
            float e01i = gr0*m2i + gi0*m2r + gr1*m3i + gi1*m3r;
            float e10r = gr1*m0r - gi1*m0i + gr0*m1r - gi0*m1i;
            float e10i = gr1*m0i + gi1*m0r + gr0*m1i + gi0*m1r;
            float e11r = gr1*m2r - gi1*m2i + gr0*m3r - gi0*m3i;
            float e11i = gr1*m2i + gi1*m2r + gr0*m3i + gi0*m3r;
            float t0r = gr0*e00r + gi0*e00i + gr1*e01r + gi1*e01i;
            float t0i = gr0*e00i - gi0*e00r + gr1*e01i - gi1*e01r;
            float t1r = gr1*e10r + gi1*e10i + gr0*e11r + gi0*e11i;
            float t1i = gr1*e10i - gi1*e10r + gr0*e11i - gi0*e11r;
            // z = N(v) t with NB = 1-NA
            float z0r = t1r + NA[v]*(t0r - t1r), z0i = t1i + NA[v]*(t0i - t1i);
            float z1r = t0r + NA[v]*(t1r - t0r), z1i = t0i + NA[v]*(t1i - t0i);
            float Sr, Si;
            if (g == gp) {
                float d0 = g ? -c0 : c0;
                Sr = d0 * (z0r - z1r); Si = d0 * (z0i - z1i);
            } else {
                Sr = -s0 * (z0r + z1r); Si = -s0 * (z0i + z1i);
            }
            o = fmaf(hw[v], Wr * Sr - Wi * Si, o);
        }
    }

    // --- wires 11 (site-0 active) and 0 (site-0 identity) from final column
    {
        float acc11 = 0.f, acc0 = 0.f;
        float mr[4] = {m0r, m1r, m2r, m3r};
        float mi[4] = {m0i, m1i, m2i, m3i};
#pragma unroll
        for (int idx = 0; idx < 4; idx++) {
            int h = idx & 1, hp = idx >> 1;
            int y = h ^ g, yp = hp ^ gp;
            float wmr = Wr * mr[idx] - Wi * mi[idx];   // Re(W·m)
            float Dv = (y == yp) ? (y ? -c0 : c0) : (-s0);
            acc11 += Dv * wmr;
            if (y == yp) acc0 += wmr;
        }
        o += hw[11] * acc11 + hw[0] * acc0;
    }

    // --- reduce the 4 column lanes (adjacent), lane col==0 writes
    o += __shfl_xor_sync(0xffffffffu, o, 1);
    o += __shfl_xor_sync(0xffffffffu, o, 2);
    if (col == 0) out[b] = o + head_b[0];
}

// ---------------------------------------------------------------------------

extern "C" void kernel_launch(void* const* d_in, const int* in_sizes, int n_in,
                              void* d_out, int out_size) {
    const float* state_batch = (const float*)d_in[0];
    const float* params      = (const float*)d_in[1];
    const float* head_w      = (const float*)d_in[2];
    const float* head_b      = (const float*)d_in[3];
    float* out = (float*)d_out;

    int threads = out_size * 4;
    int blocks = (threads + TPB - 1) / TPB;
    qtm_kernel<<<blocks, TPB>>>(state_batch, params, head_w, head_b, out, out_size);
}